// round 10
// baseline (speedup 1.0000x reference)
#include <cuda_runtime.h>
#include <float.h>

// Fixed shapes from reference setup_inputs
#define BATCH 4
#define NQ 8192
#define NK 2048
#define CH 128
#define TPB 128
#define GQ 4                          // queries per thread group member
#define SPLIT 16                      // key-split threads per query group
#define PAIRS (NK / 2)                // 1024 key-pairs
#define NCHUNK 2
#define CPAIRS (PAIRS / NCHUNK)       // 512 pairs per chunk
#define GPC 4                         // 16-key groups per thread per chunk
#define QPB (TPB / SPLIT * GQ)        // 32 queries per block

// packed f32x2 fma (sm_100+; ptxas never emits from plain C++)
#define F32X2_FMA(d, a, b, c) \
    asm("fma.rn.f32x2 %0, %1, %2, %3;" : "=l"(d) : "l"(a), "l"(b), "l"(c))

__device__ __forceinline__ unsigned long long packf2(float lo, float hi) {
    unsigned long long r;
    asm("mov.b64 %0, {%1, %2};" : "=l"(r) : "f"(lo), "f"(hi));
    return r;
}
__device__ __forceinline__ float lo32(unsigned long long v) {
    return __uint_as_float((unsigned)v);
}
__device__ __forceinline__ float hi32(unsigned long long v) {
    return __uint_as_float((unsigned)(v >> 32));
}

// packed s' = ||k||^2 - 2 q.k for a key pair. Op order: z, then y, then x.
// Scalar rescan MUST mirror this order for bitwise identity.
__device__ __forceinline__ unsigned long long dist2pk(
    ulonglong2 XY, ulonglong2 ZW,
    unsigned long long qx, unsigned long long qy, unsigned long long qz)
{
    unsigned long long acc;
    F32X2_FMA(acc, qz, ZW.x, ZW.y);
    F32X2_FMA(acc, qy, XY.y, acc);
    F32X2_FMA(acc, qx, XY.x, acc);
    return acc;
}

// Branchless insert of (m, g) into value-sorted triple with parallel ids.
// Strict < keeps the earlier entry on ties.
__device__ __forceinline__ void ins3_idx(float m, int g,
                                         float& d0, float& d1, float& d2,
                                         int& i0, int& i1, int& i2)
{
    bool p0 = m < d0;
    float h = fmaxf(m, d0);  d0 = fminf(m, d0);
    int ih = p0 ? i0 : g;    i0 = p0 ? g : i0;
    bool p1 = h < d1;
    float h1 = fmaxf(h, d1); d1 = fminf(h, d1);
    int ih1 = p1 ? i1 : ih;  i1 = p1 ? ih : i1;
    bool p2 = h1 < d2;
    d2 = fminf(h1, d2);      i2 = p2 ? ih1 : i2;
}

// Merge sorted triple (e*, j*) into sorted triple (d*, i*), keep 3 smallest.
__device__ __forceinline__ void merge_tri_idx(
    float e0, float e1, float e2, int j0, int j1, int j2,
    float& d0, float& d1, float& d2, int& i0, int& i1, int& i2)
{
    bool pd = d0 <= e0;
    float o0 = fminf(d0, e0); int o0i = pd ? i0 : j0;
    float A  = fmaxf(d0, e0); int iA  = pd ? j0 : i0;
    bool pB = d1 <= e1;
    float Bv = fminf(d1, e1); int iB  = pB ? i1 : j1;
    bool pab = A <= Bv;
    float o1 = fminf(A, Bv);  int o1i = pab ? iA : iB;
    float C  = fmaxf(A, Bv);  int iC  = pab ? iB : iA;
    float D  = fmaxf(d1, e1); int iD  = pB ? j1 : i1;
    bool pE = d2 <= e2;
    float E  = fminf(d2, e2); int iE  = pE ? i2 : j2;
    bool pF = D <= E;
    float F  = fminf(D, E);   int iF  = pF ? iD : iE;
    bool pO = C <= F;
    float o2 = fminf(C, F);   int o2i = pO ? iC : iF;
    d0 = o0; d1 = o1; d2 = o2;
    i0 = o0i; i1 = o1i; i2 = o2i;
}

__global__ __launch_bounds__(TPB, 7)
void fp_knn_interp_kernel(const float* __restrict__ xyz_q,
                          const float* __restrict__ xyz_k,
                          const float* __restrict__ v_k,
                          float* __restrict__ out)
{
    __shared__ ulonglong2 sXY[CPAIRS];   // 8 KB
    __shared__ ulonglong2 sZW[CPAIRS];   // 8 KB
    __shared__ int   soct[QPB][3];       // selected group ids per query
    __shared__ float scv[QPB][3][3];     // rescan candidate values
    __shared__ int   sck[QPB][3][3];     // rescan candidate key indices
    __shared__ int   sidx[QPB][3];
    __shared__ float swgt[QPB][3];

    const int b   = blockIdx.y;
    const int q0  = blockIdx.x * QPB;
    const int tid = threadIdx.x;
    const float* kb = xyz_k + (size_t)b * NK * 3;

    const int g  = tid >> 4;        // query group within block
    const int L  = tid & 15;        // key-split id 0..15
    const int qb = q0 + g * GQ;

    unsigned long long qxp[GQ], qyp[GQ], qzp[GQ];
    #pragma unroll
    for (int t = 0; t < GQ; ++t) {
        const float* qp = xyz_q + ((size_t)b * NQ + qb + t) * 3;
        float qx2 = -2.0f * qp[0], qy2 = -2.0f * qp[1], qz2 = -2.0f * qp[2];
        qxp[t] = packf2(qx2, qx2);
        qyp[t] = packf2(qy2, qy2);
        qzp[t] = packf2(qz2, qz2);
    }

    // running top-3 group-mins with local group ids (0..7)
    float d0[GQ], d1[GQ], d2[GQ];
    int   i0[GQ], i1[GQ], i2[GQ];
    #pragma unroll
    for (int t = 0; t < GQ; ++t) {
        d0[t] = FLT_MAX; d1[t] = FLT_MAX; d2[t] = FLT_MAX;
        i0[t] = 0; i1[t] = 0; i2[t] = 0;
    }

    // ============ pass 1: top-3 sixteen-key-group minima (with ids) ========
    for (int c = 0; c < NCHUNK; ++c) {
        __syncthreads();
        const float* kc = kb + (size_t)c * CPAIRS * 6;
        for (int p = tid; p < CPAIRS; p += TPB) {
            const float2* k2 = (const float2*)(kc + 6 * p);
            float2 A = k2[0];                 // x0 y0
            float2 Bv = k2[1];                // z0 x1
            float2 Cv = k2[2];                // y1 z1
            float w0 = fmaf(A.x, A.x, fmaf(A.y, A.y, Bv.x * Bv.x));
            float w1 = fmaf(Bv.y, Bv.y, fmaf(Cv.x, Cv.x, Cv.y * Cv.y));
            sXY[p] = make_ulonglong2(packf2(A.x, Bv.y), packf2(A.y, Cv.x));
            sZW[p] = make_ulonglong2(packf2(Bv.x, Cv.y), packf2(w0, w1));
        }
        __syncthreads();

        for (int gg = 0; gg < GPC; ++gg) {
            const int pc0 = (8 * gg) * SPLIT + L;   // first pair of group
            float ma[GQ], mb[GQ];                   // two alternating accums
            #pragma unroll
            for (int r = 0; r < 8; ++r) {
                ulonglong2 XY = sXY[pc0 + r * SPLIT];  // conflict-free LDS.128
                ulonglong2 ZW = sZW[pc0 + r * SPLIT];
                #pragma unroll
                for (int t = 0; t < GQ; ++t) {
                    unsigned long long s2 =
                        dist2pk(XY, ZW, qxp[t], qyp[t], qzp[t]);
                    float pm = fminf(lo32(s2), hi32(s2));
                    if (r == 0)           ma[t] = pm;
                    else if (r == 1)      mb[t] = pm;
                    else if ((r & 1) == 0) ma[t] = fminf(ma[t], pm);
                    else                   mb[t] = fminf(mb[t], pm);
                }
            }
            const int grp = c * GPC + gg;            // local group id 0..7
            #pragma unroll
            for (int t = 0; t < GQ; ++t)
                ins3_idx(fminf(ma[t], mb[t]), grp,
                         d0[t], d1[t], d2[t], i0[t], i1[t], i2[t]);
        }
    }

    // globalize group ids: global = local*16 + L  (0..127)
    #pragma unroll
    for (int t = 0; t < GQ; ++t) {
        i0[t] = i0[t] * SPLIT + L;
        i1[t] = i1[t] * SPLIT + L;
        i2[t] = i2[t] * SPLIT + L;
    }

    // butterfly merge across the 16 split threads (ids travel with values)
    #pragma unroll
    for (int m = 1; m < SPLIT; m <<= 1) {
        #pragma unroll
        for (int t = 0; t < GQ; ++t) {
            float e0 = __shfl_xor_sync(0xffffffffu, d0[t], m);
            float e1 = __shfl_xor_sync(0xffffffffu, d1[t], m);
            float e2 = __shfl_xor_sync(0xffffffffu, d2[t], m);
            int   j0 = __shfl_xor_sync(0xffffffffu, i0[t], m);
            int   j1 = __shfl_xor_sync(0xffffffffu, i1[t], m);
            int   j2 = __shfl_xor_sync(0xffffffffu, i2[t], m);
            merge_tri_idx(e0, e1, e2, j0, j1, j2,
                          d0[t], d1[t], d2[t], i0[t], i1[t], i2[t]);
        }
    }

    // publish selected group ids (all lanes hold identical merged triples)
    if (L == 0) {
        #pragma unroll
        for (int t = 0; t < GQ; ++t) {
            soct[g * GQ + t][0] = i0[t];
            soct[g * GQ + t][1] = i1[t];
            soct[g * GQ + t][2] = i2[t];
        }
    }
    __syncwarp();

    // ========== rescan: 3 groups x 16 keys per query, from gmem ============
    {
        const int t    = L >> 2;       // query within group
        const int slot = L & 3;        // group slot (3 = merger thread)
        if (slot < 3) {
            const int o  = soct[g * GQ + t][slot];
            const int lg = o >> 4;               // local group id 0..7
            const int Ls = o & 15;               // source thread
            const int c  = lg >> 2;
            const int gg = lg & 3;
            // reload query coords: identical input bits -> identical -2*q
            const float* qp = xyz_q + ((size_t)b * NQ + qb + t) * 3;
            const float qx2 = -2.0f * qp[0];
            const float qy2 = -2.0f * qp[1];
            const float qz2 = -2.0f * qp[2];
            float v0 = FLT_MAX, v1 = FLT_MAX, v2 = FLT_MAX;
            int   k0 = 0, k1 = 0, k2i = 0;
            #pragma unroll
            for (int r = 0; r < 8; ++r) {
                const int P = c * CPAIRS + (8 * gg + r) * SPLIT + Ls;
                const float2* K2 = (const float2*)(kb + 6 * P);
                float2 A = K2[0], Bv = K2[1], Cv = K2[2];
                // same expressions as staging / packed pipeline -> same bits
                float kk0 = fmaf(A.x, A.x, fmaf(A.y, A.y, Bv.x * Bv.x));
                float kk1 = fmaf(Bv.y, Bv.y, fmaf(Cv.x, Cv.x, Cv.y * Cv.y));
                float s0 = fmaf(qx2, A.x,  fmaf(qy2, A.y,  fmaf(qz2, Bv.x, kk0)));
                float s1 = fmaf(qx2, Bv.y, fmaf(qy2, Cv.x, fmaf(qz2, Cv.y, kk1)));
                ins3_idx(s0, 2 * P,     v0, v1, v2, k0, k1, k2i);
                ins3_idx(s1, 2 * P + 1, v0, v1, v2, k0, k1, k2i);
            }
            const int q = g * GQ + t;
            scv[q][slot][0] = v0; scv[q][slot][1] = v1; scv[q][slot][2] = v2;
            sck[q][slot][0] = k0; sck[q][slot][1] = k1; sck[q][slot][2] = k2i;
        }
    }
    __syncwarp();

    // ---- final: merge 9 candidates per query, compute weights -------------
    if ((L & 3) == 3) {
        const int t = L >> 2;
        const int q = g * GQ + t;
        float bv0 = FLT_MAX, bv1 = FLT_MAX, bv2 = FLT_MAX;
        int   bk0 = 0x7FFFFFFF, bk1 = 0x7FFFFFFF, bk2 = 0x7FFFFFFF;
        #pragma unroll
        for (int s = 0; s < 3; ++s) {
            #pragma unroll
            for (int r = 0; r < 3; ++r) {
                float v = scv[q][s][r];
                int   k = sck[q][s][r];
                bool lt2 = (v < bv2) || (v == bv2 && k < bk2);
                if (lt2) {
                    bool lt1 = (v < bv1) || (v == bv1 && k < bk1);
                    if (lt1) {
                        bv2 = bv1; bk2 = bk1;
                        bool lt0 = (v < bv0) || (v == bv0 && k < bk0);
                        if (lt0) { bv1 = bv0; bk1 = bk0; bv0 = v; bk0 = k; }
                        else     { bv1 = v;   bk1 = k; }
                    } else { bv2 = v; bk2 = k; }
                }
            }
        }
        const float* qp = xyz_q + ((size_t)b * NQ + qb + t) * 3;
        float qq = fmaf(qp[0], qp[0], fmaf(qp[1], qp[1], qp[2] * qp[2]));
        float w0 = 1.0f / fmaxf(bv0 + qq, 1e-10f);
        float w1 = 1.0f / fmaxf(bv1 + qq, 1e-10f);
        float w2 = 1.0f / fmaxf(bv2 + qq, 1e-10f);
        float inv_sum = 1.0f / (w0 + w1 + w2);
        sidx[q][0] = bk0; sidx[q][1] = bk1; sidx[q][2] = bk2;
        swgt[q][0] = w0 * inv_sum;
        swgt[q][1] = w1 * inv_sum;
        swgt[q][2] = w2 * inv_sum;
    }
    __syncthreads();

    // ---- gather epilogue: one warp per query, lane = channel quad ----------
    const float4* vb = (const float4*)(v_k + (size_t)b * NK * CH);
    float4* ob = (float4*)(out + ((size_t)b * NQ + q0) * CH);
    const int lane = tid & 31;
    const int warp = tid >> 5;

    #pragma unroll
    for (int ql = warp; ql < QPB; ql += TPB / 32) {
        int   n0 = sidx[ql][0], n1 = sidx[ql][1], n2 = sidx[ql][2];
        float a0 = swgt[ql][0], a1 = swgt[ql][1], a2 = swgt[ql][2];
        float4 va = vb[n0 * (CH / 4) + lane];
        float4 vc = vb[n1 * (CH / 4) + lane];
        float4 vd = vb[n2 * (CH / 4) + lane];
        float4 r;
        r.x = a0 * va.x + a1 * vc.x + a2 * vd.x;
        r.y = a0 * va.y + a1 * vc.y + a2 * vd.y;
        r.z = a0 * va.z + a1 * vc.z + a2 * vd.z;
        r.w = a0 * va.w + a1 * vc.w + a2 * vd.w;
        ob[ql * (CH / 4) + lane] = r;
    }
}

extern "C" void kernel_launch(void* const* d_in, const int* in_sizes, int n_in,
                              void* d_out, int out_size)
{
    const float* xyz_q = (const float*)d_in[0];   // [4, 8192, 3]
    const float* xyz_k = (const float*)d_in[1];   // [4, 2048, 3]
    const float* v_k   = (const float*)d_in[2];   // [4, 2048, 128]
    float* out = (float*)d_out;                   // [4, 8192, 128]

    dim3 grid(NQ / QPB, BATCH);   // (256, 4) = 1024 CTAs, single wave at occ 7
    fp_knn_interp_kernel<<<grid, TPB>>>(xyz_q, xyz_k, v_k, out);
}